// round 1
// baseline (speedup 1.0000x reference)
#include <cuda_runtime.h>
#include <math.h>

#define NB    8
#define TT    2048
#define BT    (NB*TT)      // 16384 rows
#define DM    256
#define DI    512
#define NST   16
#define EPS   1e-5f

// ---------------- scratch (device globals: no allocation allowed) ----------------
__device__ float g_h[BT*DM];        // residual stream
__device__ float g_u[BT*DM];        // rmsnorm output
__device__ float g_xz[BT*2*DI];     // in_proj output (xi | z)
__device__ float g_xc[BT*DI];       // conv+silu output
__device__ float g_dbc[BT*48];      // x_proj output (dt_in | B | C)
__device__ float g_delta[BT*DI];    // softplus(dt)
__device__ float g_y[BT*DI];        // scan output (post gate)
__device__ float g_past[BT];        // past_soc

// ---------------- helpers ----------------
__device__ __forceinline__ float blockReduceSum256(float v, float* sh) {
    int lane = threadIdx.x & 31, wid = threadIdx.x >> 5;
    #pragma unroll
    for (int o = 16; o; o >>= 1) v += __shfl_xor_sync(0xffffffffu, v, o);
    __syncthreads();              // protect sh reuse across calls
    if (lane == 0) sh[wid] = v;
    __syncthreads();
    float s = 0.f;
    #pragma unroll
    for (int i = 0; i < 8; i++) s += sh[i];
    return s;
}

__device__ __forceinline__ float siluf(float x) {
    return x / (1.f + __expf(-x));
}

// ---------------- kernel 1: input proj + layernorm + past_soc ----------------
__global__ __launch_bounds__(256) void k_embed(
    const float* __restrict__ x, const float* __restrict__ ipw,
    const float* __restrict__ ipb, const float* __restrict__ lng,
    const float* __restrict__ lnb)
{
    __shared__ float xs[10];
    __shared__ float red[8];
    int row = blockIdx.x;
    int m = threadIdx.x;
    if (m < 10) xs[m] = x[row*10 + m];
    __syncthreads();
    float s = ipb[m];
    #pragma unroll
    for (int i = 0; i < 10; i++) s += xs[i] * ipw[m*10 + i];
    float mean = blockReduceSum256(s, red) * (1.f/256.f);
    float d = s - mean;
    float var = blockReduceSum256(d*d, red) * (1.f/256.f);
    g_h[row*DM + m] = d * rsqrtf(var + EPS) * lng[m] + lnb[m];
    if (m == 0) g_past[row] = xs[9];
}

// ---------------- kernel 2: rmsnorm of residual stream -> g_u ----------------
__global__ __launch_bounds__(256) void k_rms(const float* __restrict__ w) {
    __shared__ float red[8];
    int row = blockIdx.x;
    int m = threadIdx.x;
    float v = g_h[row*DM + m];
    float ms = blockReduceSum256(v*v, red) * (1.f/256.f);
    g_u[row*DM + m] = v * rsqrtf(ms + EPS) * w[m];
}

// ---------------- kernel 3: generic NT SGEMM  C[i,j] (+)= sum_k A[i,k]*B[j,k] ----
// BM=BN=128, BK=8, 256 threads, 8x8 per thread. EPI 0: store, EPI 1: accumulate.
template<int EPI>
__global__ __launch_bounds__(256) void k_sgemm_nt(
    const float* __restrict__ A, const float* __restrict__ Bm,
    float* __restrict__ C, int M, int N, int K)
{
    __shared__ float As[8][128];
    __shared__ float Bs[8][128];
    int tid = threadIdx.x;
    int mBase = blockIdx.y * 128, nBase = blockIdx.x * 128;
    int lr = tid >> 1;          // 0..127
    int lk = (tid & 1) * 4;     // 0 or 4
    const float* Ag = A + (size_t)(mBase + lr)*K + lk;
    const float* Bg = Bm + (size_t)(nBase + lr)*K + lk;
    int ty = tid >> 4, tx = tid & 15;
    float acc[8][8];
    #pragma unroll
    for (int i = 0; i < 8; i++)
        #pragma unroll
        for (int j = 0; j < 8; j++) acc[i][j] = 0.f;

    for (int kb = 0; kb < K; kb += 8) {
        float4 av = *(const float4*)(Ag + kb);
        float4 bv = *(const float4*)(Bg + kb);
        __syncthreads();
        As[lk+0][lr] = av.x; As[lk+1][lr] = av.y; As[lk+2][lr] = av.z; As[lk+3][lr] = av.w;
        Bs[lk+0][lr] = bv.x; Bs[lk+1][lr] = bv.y; Bs[lk+2][lr] = bv.z; Bs[lk+3][lr] = bv.w;
        __syncthreads();
        #pragma unroll
        for (int k = 0; k < 8; k++) {
            float a[8], b[8];
            *(float4*)(a)   = *(const float4*)&As[k][ty*8];
            *(float4*)(a+4) = *(const float4*)&As[k][ty*8+4];
            *(float4*)(b)   = *(const float4*)&Bs[k][tx*8];
            *(float4*)(b+4) = *(const float4*)&Bs[k][tx*8+4];
            #pragma unroll
            for (int i = 0; i < 8; i++)
                #pragma unroll
                for (int j = 0; j < 8; j++) acc[i][j] += a[i]*b[j];
        }
    }
    #pragma unroll
    for (int i = 0; i < 8; i++) {
        int m = mBase + ty*8 + i;
        float* Cp = C + (size_t)m*N + nBase + tx*8;
        if (EPI == 0) {
            float4 v0 = make_float4(acc[i][0],acc[i][1],acc[i][2],acc[i][3]);
            float4 v1 = make_float4(acc[i][4],acc[i][5],acc[i][6],acc[i][7]);
            *(float4*)(Cp)   = v0;
            *(float4*)(Cp+4) = v1;
        } else {
            #pragma unroll
            for (int j = 0; j < 8; j++) Cp[j] += acc[i][j];
        }
    }
}

// ---------------- kernel 4: causal depthwise conv(4) + bias + silu ----------------
__global__ __launch_bounds__(256) void k_conv(
    const float* __restrict__ cw, const float* __restrict__ cb)
{
    int idx = blockIdx.x * blockDim.x + threadIdx.x;   // BT*DI
    int d = idx & (DI-1);
    int row = idx >> 9;
    int t = row & (TT-1);
    float acc = cb[d];
    const float* w = cw + d*4;
    #pragma unroll
    for (int k = 0; k < 4; k++) {
        int tt = t - 3 + k;
        if (tt >= 0) acc += w[k] * g_xz[(size_t)(row - 3 + k)*1024 + d];
    }
    g_xc[idx] = siluf(acc);
}

// ---------------- kernel 5: x_proj  dbc[row,0:48] = xc[row,:] @ xpw^T ------------
// 8 rows per block, warp per row; xc row staged in smem, xpw via L1 (shared across warps)
__global__ __launch_bounds__(256) void k_dbc(const float* __restrict__ xpw) {
    __shared__ float xs[8][512];
    int r0 = blockIdx.x * 8;
    int tid = threadIdx.x;
    const float4* src = (const float4*)(g_xc + (size_t)r0*512);
    float4* dst = (float4*)&xs[0][0];
    #pragma unroll
    for (int i = 0; i < 4; i++) dst[tid + 256*i] = src[tid + 256*i];
    __syncthreads();
    int w = tid >> 5, lane = tid & 31;
    const float4* xr = (const float4*)xs[w];
    const float4* wp = (const float4*)xpw;
    for (int e = 0; e < 48; e++) {
        float s = 0.f;
        #pragma unroll
        for (int i = 0; i < 4; i++) {
            float4 xv = xr[lane + 32*i];
            float4 wv = __ldg(&wp[e*128 + lane + 32*i]);
            s += xv.x*wv.x + xv.y*wv.y + xv.z*wv.z + xv.w*wv.w;
        }
        #pragma unroll
        for (int o = 16; o; o >>= 1) s += __shfl_xor_sync(0xffffffffu, s, o);
        if (lane == 0) g_dbc[(size_t)(r0 + w)*48 + e] = s;
    }
}

// ---------------- kernel 6: dt_proj + softplus -> g_delta ----------------
__global__ __launch_bounds__(256) void k_delta(
    const float* __restrict__ dtw, const float* __restrict__ dtb)
{
    int idx = blockIdx.x * blockDim.x + threadIdx.x;   // BT*DI
    int d = idx & (DI-1);
    int row = idx >> 9;
    const float4* dr = (const float4*)(g_dbc + (size_t)row*48);
    const float4* wr = (const float4*)(dtw + d*16);
    float acc = dtb[d];
    #pragma unroll
    for (int c = 0; c < 4; c++) {
        float4 dv = dr[c];
        float4 wv = __ldg(&wr[c]);
        acc += dv.x*wv.x + dv.y*wv.y + dv.z*wv.z + dv.w*wv.w;
    }
    g_delta[idx] = (acc > 20.f) ? acc : log1pf(__expf(acc));
}

// ---------------- kernel 7: selective scan + D skip + gate ----------------
// one warp per (b,d); lanes 0..15 hold the 16 states, lanes 16..31 mirror them.
__global__ __launch_bounds__(256) void k_scan(
    const float* __restrict__ A_log, const float* __restrict__ Dp)
{
    int gw = (blockIdx.x * blockDim.x + threadIdx.x) >> 5;   // 0..4095
    int lane = threadIdx.x & 31;
    int n = lane & 15;
    int b = gw >> 9;
    int d = gw & (DI-1);
    float na = -__expf(A_log[d*16 + n]);
    float Dv = Dp[d];
    float h = 0.f;
    size_t base = (size_t)b * TT;
    for (int t = 0; t < TT; t++) {
        size_t row = base + t;
        float dl = __ldg(&g_delta[row*512 + d]);
        float xi = __ldg(&g_xc[row*512 + d]);
        float Bv = __ldg(&g_dbc[row*48 + 16 + n]);
        float Cv = __ldg(&g_dbc[row*48 + 32 + n]);
        float da = __expf(dl * na);
        h = da*h + (dl*xi)*Bv;
        float v = h * Cv;
        #pragma unroll
        for (int o = 8; o; o >>= 1) v += __shfl_xor_sync(0xffffffffu, v, o);
        if (lane == 0) {
            float z = g_xz[row*1024 + 512 + d];
            float y = v + Dv*xi;
            g_y[row*512 + d] = y * siluf(z);
        }
    }
}

// ---------------- kernel 8: final rmsnorm + head + output ----------------
__global__ __launch_bounds__(256) void k_final(
    const float* __restrict__ fw, const float* __restrict__ hw,
    const float* __restrict__ hb, float* __restrict__ out)
{
    __shared__ float red[8];
    int row = blockIdx.x;
    int m = threadIdx.x;
    float v = g_h[row*DM + m];
    float ms = blockReduceSum256(v*v, red) * (1.f/256.f);
    float hn = v * rsqrtf(ms + EPS) * fw[m];
    float dot = blockReduceSum256(hn * hw[m], red);
    if (m == 0) {
        float dlt = dot + hb[0];
        out[row] = g_past[row] + dlt;      // y
        out[BT + row] = dlt;               // delta
    }
}

// ---------------- host launcher ----------------
extern "C" void kernel_launch(void* const* d_in, const int* in_sizes, int n_in,
                              void* d_out, int out_size)
{
    const float* x    = (const float*)d_in[0];
    const float* ipw  = (const float*)d_in[1];
    const float* ipb  = (const float*)d_in[2];
    const float* lng  = (const float*)d_in[3];
    const float* lnb  = (const float*)d_in[4];
    const float* inpw = (const float*)d_in[5];   // (2,1024,256)
    const float* cw   = (const float*)d_in[6];   // (2,512,1,4)
    const float* cb   = (const float*)d_in[7];   // (2,512)
    const float* xpw  = (const float*)d_in[8];   // (2,48,512)
    const float* dtw  = (const float*)d_in[9];   // (2,512,16)
    const float* dtb  = (const float*)d_in[10];  // (2,512)
    const float* alog = (const float*)d_in[11];  // (2,512,16)
    const float* dpar = (const float*)d_in[12];  // (2,512)
    const float* opw  = (const float*)d_in[13];  // (2,256,512)
    const float* rmsw = (const float*)d_in[14];  // (2,256)
    const float* frw  = (const float*)d_in[15];  // (256)
    const float* hw   = (const float*)d_in[16];  // (1,256)
    const float* hb   = (const float*)d_in[17];  // (1)
    float* out = (float*)d_out;

    float *pu, *pxz, *py, *ph;
    cudaGetSymbolAddress((void**)&pu,  g_u);
    cudaGetSymbolAddress((void**)&pxz, g_xz);
    cudaGetSymbolAddress((void**)&py,  g_y);
    cudaGetSymbolAddress((void**)&ph,  g_h);

    k_embed<<<BT, 256>>>(x, ipw, ipb, lng, lnb);

    for (int l = 0; l < 2; l++) {
        k_rms<<<BT, 256>>>(rmsw + l*DM);
        k_sgemm_nt<0><<<dim3(1024/128, BT/128), 256>>>(pu, inpw + (size_t)l*1024*256, pxz, BT, 1024, 256);
        k_conv<<<BT*DI/256, 256>>>(cw + l*DI*4, cb + l*DI);
        k_dbc<<<BT/8, 256>>>(xpw + l*48*512);
        k_delta<<<BT*DI/256, 256>>>(dtw + l*DI*16, dtb + l*DI);
        k_scan<<<512, 256>>>(alog + l*DI*16, dpar + l*DI);
        k_sgemm_nt<1><<<dim3(256/128, BT/128), 256>>>(py, opw + (size_t)l*256*512, ph, BT, 256, 512);
    }

    k_final<<<BT, 256>>>(frw, hw, hb, out);
}

// round 2
// speedup vs baseline: 1.0504x; 1.0504x over previous
#include <cuda_runtime.h>
#include <math.h>

#define NB    8
#define TT    2048
#define BT    (NB*TT)      // 16384 rows
#define DM    256
#define DI    512
#define EPS   1e-5f

// ---------------- scratch (device globals: no allocation allowed) ----------------
__device__ float g_h[BT*DM];        // residual stream
__device__ float g_u[BT*DM];        // rmsnorm output
__device__ float g_xz[BT*2*DI];     // in_proj output (xi | z)
__device__ float g_xc[BT*DI];       // conv+silu output
__device__ float g_dbc[BT*48];      // x_proj output (dt_in | B | C)
__device__ float g_delta[BT*DI];    // softplus(dt)
__device__ float g_y[BT*DI];        // scan output (post gate)
__device__ float g_past[BT];        // past_soc

// ---------------- helpers ----------------
__device__ __forceinline__ float blockReduceSum256(float v, float* sh) {
    int lane = threadIdx.x & 31, wid = threadIdx.x >> 5;
    #pragma unroll
    for (int o = 16; o; o >>= 1) v += __shfl_xor_sync(0xffffffffu, v, o);
    __syncthreads();
    if (lane == 0) sh[wid] = v;
    __syncthreads();
    float s = 0.f;
    #pragma unroll
    for (int i = 0; i < 8; i++) s += sh[i];
    return s;
}

__device__ __forceinline__ float siluf(float x) {
    return x / (1.f + __expf(-x));
}

// ---------------- kernel 1: input proj + layernorm + past_soc ----------------
__global__ __launch_bounds__(256) void k_embed(
    const float* __restrict__ x, const float* __restrict__ ipw,
    const float* __restrict__ ipb, const float* __restrict__ lng,
    const float* __restrict__ lnb)
{
    __shared__ float xs[10];
    __shared__ float red[8];
    int row = blockIdx.x;
    int m = threadIdx.x;
    if (m < 10) xs[m] = x[row*10 + m];
    __syncthreads();
    float s = ipb[m];
    #pragma unroll
    for (int i = 0; i < 10; i++) s += xs[i] * ipw[m*10 + i];
    float mean = blockReduceSum256(s, red) * (1.f/256.f);
    float d = s - mean;
    float var = blockReduceSum256(d*d, red) * (1.f/256.f);
    g_h[row*DM + m] = d * rsqrtf(var + EPS) * lng[m] + lnb[m];
    if (m == 0) g_past[row] = xs[9];
}

// ---------------- kernel 2: rmsnorm of residual stream -> g_u ----------------
__global__ __launch_bounds__(256) void k_rms(const float* __restrict__ w) {
    __shared__ float red[8];
    int row = blockIdx.x;
    int m = threadIdx.x;
    float v = g_h[row*DM + m];
    float ms = blockReduceSum256(v*v, red) * (1.f/256.f);
    g_u[row*DM + m] = v * rsqrtf(ms + EPS) * w[m];
}

// ---------------- kernel 3: NT SGEMM, 128x128x8, double-buffered -----------------
// C[i,j] (+)= sum_k A[i,k]*B[j,k].  EPI 0: store, EPI 1: accumulate into C.
// warps: 2(M) x 4(N); threads in warp: 8(M) x 4(N); thread tile 8x8 split 4+4.
template<int EPI>
__global__ __launch_bounds__(256) void k_sgemm_nt(
    const float* __restrict__ A, const float* __restrict__ Bm,
    float* __restrict__ C, int M, int N, int K)
{
    __shared__ float As[2][8][128];
    __shared__ float Bs[2][8][128];
    int tid = threadIdx.x;
    int mBase = blockIdx.y * 128, nBase = blockIdx.x * 128;

    // global->smem loader mapping: 128 rows x 8 k per tile, float4 per thread
    int lr = tid >> 1;              // 0..127
    int lk = (tid & 1) * 4;         // 0 or 4
    const float* Ag = A + (size_t)(mBase + lr)*K + lk;
    const float* Bg = Bm + (size_t)(nBase + lr)*K + lk;

    // compute mapping
    int warp = tid >> 5, lane = tid & 31;
    int wm = warp & 1, wn = warp >> 1;        // 2 x 4 warp grid
    int tm = lane & 7, tn = lane >> 3;        // 8 x 4 thread grid
    int aoff = wm*64 + tm*4;                  // + {0..3}, and +32
    int boff = wn*32 + tn*4;                  // + {0..3}, and +16

    float acc[8][8];
    #pragma unroll
    for (int i = 0; i < 8; i++)
        #pragma unroll
        for (int j = 0; j < 8; j++) acc[i][j] = 0.f;

    // prologue: load first chunk, store to buffer 0
    float4 pa = *(const float4*)Ag;
    float4 pb = *(const float4*)Bg;
    As[0][lk+0][lr] = pa.x; As[0][lk+1][lr] = pa.y;
    As[0][lk+2][lr] = pa.z; As[0][lk+3][lr] = pa.w;
    Bs[0][lk+0][lr] = pb.x; Bs[0][lk+1][lr] = pb.y;
    Bs[0][lk+2][lr] = pb.z; Bs[0][lk+3][lr] = pb.w;
    __syncthreads();

    int buf = 0;
    for (int kb = 8; kb <= K; kb += 8) {
        if (kb < K) {
            pa = *(const float4*)(Ag + kb);
            pb = *(const float4*)(Bg + kb);
        }
        #pragma unroll
        for (int k = 0; k < 8; k++) {
            float a[8], b[8];
            *(float4*)(a)   = *(const float4*)&As[buf][k][aoff];
            *(float4*)(a+4) = *(const float4*)&As[buf][k][aoff+32];
            *(float4*)(b)   = *(const float4*)&Bs[buf][k][boff];
            *(float4*)(b+4) = *(const float4*)&Bs[buf][k][boff+16];
            #pragma unroll
            for (int i = 0; i < 8; i++)
                #pragma unroll
                for (int j = 0; j < 8; j++) acc[i][j] += a[i]*b[j];
        }
        if (kb < K) {
            buf ^= 1;
            As[buf][lk+0][lr] = pa.x; As[buf][lk+1][lr] = pa.y;
            As[buf][lk+2][lr] = pa.z; As[buf][lk+3][lr] = pa.w;
            Bs[buf][lk+0][lr] = pb.x; Bs[buf][lk+1][lr] = pb.y;
            Bs[buf][lk+2][lr] = pb.z; Bs[buf][lk+3][lr] = pb.w;
            __syncthreads();
        }
    }

    // epilogue
    #pragma unroll
    for (int i = 0; i < 8; i++) {
        int mloc = wm*64 + ((i < 4) ? (tm*4 + i) : (32 + tm*4 + i - 4));
        float* Cp = C + (size_t)(mBase + mloc)*N + nBase;
        if (EPI == 0) {
            *(float4*)(Cp + boff)      = make_float4(acc[i][0],acc[i][1],acc[i][2],acc[i][3]);
            *(float4*)(Cp + boff + 16) = make_float4(acc[i][4],acc[i][5],acc[i][6],acc[i][7]);
        } else {
            float4 c0 = *(const float4*)(Cp + boff);
            float4 c1 = *(const float4*)(Cp + boff + 16);
            c0.x += acc[i][0]; c0.y += acc[i][1]; c0.z += acc[i][2]; c0.w += acc[i][3];
            c1.x += acc[i][4]; c1.y += acc[i][5]; c1.z += acc[i][6]; c1.w += acc[i][7];
            *(float4*)(Cp + boff)      = c0;
            *(float4*)(Cp + boff + 16) = c1;
        }
    }
}

// ---------------- kernel 4: causal depthwise conv(4) + bias + silu ---------------
// 4 consecutive t per thread: 7 loads -> 4 outputs.
__global__ __launch_bounds__(256) void k_conv(
    const float* __restrict__ cw, const float* __restrict__ cb)
{
    int idx = blockIdx.x * blockDim.x + threadIdx.x;   // BT*DI/4
    int d = idx & (DI-1);
    int rq = idx >> 9;                 // (b, t/4) group, 0..BT/4-1
    int tq = rq & (TT/4 - 1);
    size_t row0 = (size_t)rq * 4;      // global row = b*TT + tq*4
    const float* w = cw + d*4;
    float w0 = w[0], w1 = w[1], w2 = w[2], w3 = w[3];
    float bias = cb[d];

    float xm3 = 0.f, xm2 = 0.f, xm1 = 0.f;
    if (tq > 0) {
        xm3 = g_xz[(row0-3)*1024 + d];
        xm2 = g_xz[(row0-2)*1024 + d];
        xm1 = g_xz[(row0-1)*1024 + d];
    }
    float x0 = g_xz[(row0+0)*1024 + d];
    float x1 = g_xz[(row0+1)*1024 + d];
    float x2 = g_xz[(row0+2)*1024 + d];
    float x3 = g_xz[(row0+3)*1024 + d];

    g_xc[(row0+0)*512 + d] = siluf(bias + w0*xm3 + w1*xm2 + w2*xm1 + w3*x0);
    g_xc[(row0+1)*512 + d] = siluf(bias + w0*xm2 + w1*xm1 + w2*x0  + w3*x1);
    g_xc[(row0+2)*512 + d] = siluf(bias + w0*xm1 + w1*x0  + w2*x1  + w3*x2);
    g_xc[(row0+3)*512 + d] = siluf(bias + w0*x0  + w1*x1  + w2*x2  + w3*x3);
}

// ---------------- kernel 5: x_proj + dt_proj + softplus (fused) ------------------
// 8 rows per block. Phase 1: warp-per-row dbc (48 dots of 512).
// Phase 2: delta[r,d] = softplus(dtb[d] + dbc[r,0:16] . dtw[d,:]).
__global__ __launch_bounds__(256) void k_dbc_delta(
    const float* __restrict__ xpw, const float* __restrict__ dtw,
    const float* __restrict__ dtb)
{
    __shared__ float xs[8][512];
    __shared__ float dbc_s[8][48];
    int r0 = blockIdx.x * 8;
    int tid = threadIdx.x;

    const float4* src = (const float4*)(g_xc + (size_t)r0*512);
    float4* dst = (float4*)&xs[0][0];
    #pragma unroll
    for (int i = 0; i < 4; i++) dst[tid + 256*i] = src[tid + 256*i];
    __syncthreads();

    int w = tid >> 5, lane = tid & 31;
    const float4* xr = (const float4*)xs[w];
    const float4* wp = (const float4*)xpw;
    for (int e = 0; e < 48; e++) {
        float s = 0.f;
        #pragma unroll
        for (int i = 0; i < 4; i++) {
            float4 xv = xr[lane + 32*i];
            float4 wv = __ldg(&wp[e*128 + lane + 32*i]);
            s += xv.x*wv.x + xv.y*wv.y + xv.z*wv.z + xv.w*wv.w;
        }
        #pragma unroll
        for (int o = 16; o; o >>= 1) s += __shfl_xor_sync(0xffffffffu, s, o);
        if (lane == 0) {
            dbc_s[w][e] = s;
            g_dbc[(size_t)(r0 + w)*48 + e] = s;
        }
    }
    __syncthreads();

    // delta: 8 rows x 512 d = 4096 outputs, 16 per thread
    #pragma unroll
    for (int i = 0; i < 16; i++) {
        int idx = i*256 + tid;
        int r = idx >> 9;
        int d = idx & (DI-1);
        const float4* wr = (const float4*)(dtw + d*16);
        const float4* dr = (const float4*)dbc_s[r];
        float acc = dtb[d];
        #pragma unroll
        for (int c = 0; c < 4; c++) {
            float4 dv = dr[c];
            float4 wv = __ldg(&wr[c]);
            acc += dv.x*wv.x + dv.y*wv.y + dv.z*wv.z + dv.w*wv.w;
        }
        g_delta[(size_t)(r0 + r)*512 + d] = (acc > 20.f) ? acc : log1pf(__expf(acc));
    }
}

// ---------------- kernel 6: selective scan + D skip + gate ----------------
// one warp per (b,d); lanes 0..15 hold states, lanes 16..31 mirror.
__global__ __launch_bounds__(256) void k_scan(
    const float* __restrict__ A_log, const float* __restrict__ Dp)
{
    int gw = (blockIdx.x * blockDim.x + threadIdx.x) >> 5;   // 0..4095
    int lane = threadIdx.x & 31;
    int n = lane & 15;
    int b = gw >> 9;
    int d = gw & (DI-1);
    float na = -__expf(A_log[d*16 + n]);
    float Dv = Dp[d];
    float h = 0.f;
    size_t base = (size_t)b * TT;
    #pragma unroll 4
    for (int t = 0; t < TT; t++) {
        size_t row = base + t;
        float dl = __ldg(&g_delta[row*512 + d]);
        float xi = __ldg(&g_xc[row*512 + d]);
        float Bv = __ldg(&g_dbc[row*48 + 16 + n]);
        float Cv = __ldg(&g_dbc[row*48 + 32 + n]);
        float da = __expf(dl * na);
        h = da*h + (dl*xi)*Bv;
        float v = h * Cv;
        #pragma unroll
        for (int o = 8; o; o >>= 1) v += __shfl_xor_sync(0xffffffffu, v, o);
        if (lane == 0) {
            float z = g_xz[row*1024 + 512 + d];
            float y = v + Dv*xi;
            g_y[row*512 + d] = y * siluf(z);
        }
    }
}

// ---------------- kernel 7: final rmsnorm + head + output ----------------
__global__ __launch_bounds__(256) void k_final(
    const float* __restrict__ fw, const float* __restrict__ hw,
    const float* __restrict__ hb, float* __restrict__ out)
{
    __shared__ float red[8];
    int row = blockIdx.x;
    int m = threadIdx.x;
    float v = g_h[row*DM + m];
    float ms = blockReduceSum256(v*v, red) * (1.f/256.f);
    float hn = v * rsqrtf(ms + EPS) * fw[m];
    float dot = blockReduceSum256(hn * hw[m], red);
    if (m == 0) {
        float dlt = dot + hb[0];
        out[row] = g_past[row] + dlt;      // y
        out[BT + row] = dlt;               // delta
    }
}

// ---------------- host launcher ----------------
extern "C" void kernel_launch(void* const* d_in, const int* in_sizes, int n_in,
                              void* d_out, int out_size)
{
    const float* x    = (const float*)d_in[0];
    const float* ipw  = (const float*)d_in[1];
    const float* ipb  = (const float*)d_in[2];
    const float* lng  = (const float*)d_in[3];
    const float* lnb  = (const float*)d_in[4];
    const float* inpw = (const float*)d_in[5];   // (2,1024,256)
    const float* cw   = (const float*)d_in[6];   // (2,512,1,4)
    const float* cb   = (const float*)d_in[7];   // (2,512)
    const float* xpw  = (const float*)d_in[8];   // (2,48,512)
    const float* dtw  = (const float*)d_in[9];   // (2,512,16)
    const float* dtb  = (const float*)d_in[10];  // (2,512)
    const float* alog = (const float*)d_in[11];  // (2,512,16)
    const float* dpar = (const float*)d_in[12];  // (2,512)
    const float* opw  = (const float*)d_in[13];  // (2,256,512)
    const float* rmsw = (const float*)d_in[14];  // (2,256)
    const float* frw  = (const float*)d_in[15];  // (256)
    const float* hw   = (const float*)d_in[16];  // (1,256)
    const float* hb   = (const float*)d_in[17];  // (1)
    float* out = (float*)d_out;

    float *pu, *pxz, *py, *ph;
    cudaGetSymbolAddress((void**)&pu,  g_u);
    cudaGetSymbolAddress((void**)&pxz, g_xz);
    cudaGetSymbolAddress((void**)&py,  g_y);
    cudaGetSymbolAddress((void**)&ph,  g_h);

    k_embed<<<BT, 256>>>(x, ipw, ipb, lng, lnb);

    for (int l = 0; l < 2; l++) {
        k_rms<<<BT, 256>>>(rmsw + l*DM);
        k_sgemm_nt<0><<<dim3(1024/128, BT/128), 256>>>(pu, inpw + (size_t)l*1024*256, pxz, BT, 1024, 256);
        k_conv<<<BT*DI/4/256, 256>>>(cw + l*DI*4, cb + l*DI);
        k_dbc_delta<<<BT/8, 256>>>(xpw + l*48*512, dtw + l*DI*16, dtb + l*DI);
        k_scan<<<512, 256>>>(alog + l*DI*16, dpar + l*DI);
        k_sgemm_nt<1><<<dim3(256/128, BT/128), 256>>>(py, opw + (size_t)l*256*512, ph, BT, 256, 512);
    }

    k_final<<<BT, 256>>>(frw, hw, hb, out);
}

// round 4
// speedup vs baseline: 2.1716x; 2.0674x over previous
#include <cuda_runtime.h>
#include <math.h>

#define NB    8
#define TT    2048
#define BT    (NB*TT)      // 16384 rows
#define DM    256
#define DI    512
#define EPS   1e-5f

// ---------------- scratch (device globals: no allocation allowed) ----------------
__device__ float g_h[BT*DM];        // residual stream
__device__ float g_u[BT*DM];        // rmsnorm output
__device__ float g_xz[BT*2*DI];     // in_proj output (xi | z)
__device__ float g_xc[BT*DI];       // conv+silu output
__device__ float g_zs[BT*DI];       // silu(z)
__device__ float g_dbc[BT*48];      // x_proj output (dt_in | B | C)
__device__ float g_delta[BT*DI];    // softplus(dt)
__device__ float g_y[BT*DI];        // scan output (post gate)
__device__ float g_past[BT];        // past_soc

// ---------------- helpers ----------------
__device__ __forceinline__ float blockReduceSum256(float v, float* sh) {
    int lane = threadIdx.x & 31, wid = threadIdx.x >> 5;
    #pragma unroll
    for (int o = 16; o; o >>= 1) v += __shfl_xor_sync(0xffffffffu, v, o);
    __syncthreads();
    if (lane == 0) sh[wid] = v;
    __syncthreads();
    float s = 0.f;
    #pragma unroll
    for (int i = 0; i < 8; i++) s += sh[i];
    return s;
}

__device__ __forceinline__ float siluf(float x) {
    return x / (1.f + __expf(-x));
}

// ---------------- kernel 0: launch-slot filler so ncu captures the SGEMM ---------
__global__ void k_warm() {}

// ---------------- kernel 1: input proj + layernorm + past_soc ----------------
__global__ __launch_bounds__(256) void k_embed(
    const float* __restrict__ x, const float* __restrict__ ipw,
    const float* __restrict__ ipb, const float* __restrict__ lng,
    const float* __restrict__ lnb)
{
    __shared__ float xs[10];
    __shared__ float red[8];
    int row = blockIdx.x;
    int m = threadIdx.x;
    if (m < 10) xs[m] = x[row*10 + m];
    __syncthreads();
    float s = ipb[m];
    #pragma unroll
    for (int i = 0; i < 10; i++) s += xs[i] * ipw[m*10 + i];
    float mean = blockReduceSum256(s, red) * (1.f/256.f);
    float d = s - mean;
    float var = blockReduceSum256(d*d, red) * (1.f/256.f);
    g_h[row*DM + m] = d * rsqrtf(var + EPS) * lng[m] + lnb[m];
    if (m == 0) g_past[row] = xs[9];
}

// ---------------- kernel 2: rmsnorm of residual stream -> g_u ----------------
__global__ __launch_bounds__(256) void k_rms(const float* __restrict__ w) {
    __shared__ float red[8];
    int row = blockIdx.x;
    int m = threadIdx.x;
    float v = g_h[row*DM + m];
    float ms = blockReduceSum256(v*v, red) * (1.f/256.f);
    g_u[row*DM + m] = v * rsqrtf(ms + EPS) * w[m];
}

// ---------------- kernel 3: NT SGEMM, 128x128x8, double-buffered -----------------
// C[i,j] (+)= sum_k A[i,k]*B[j,k].  EPI 0: store, EPI 1: accumulate into C.
template<int EPI>
__global__ __launch_bounds__(256) void k_sgemm_nt(
    const float* __restrict__ A, const float* __restrict__ Bm,
    float* __restrict__ C, int M, int N, int K)
{
    __shared__ float As[2][8][128];
    __shared__ float Bs[2][8][128];
    int tid = threadIdx.x;
    int mBase = blockIdx.y * 128, nBase = blockIdx.x * 128;

    int lr = tid >> 1;              // 0..127
    int lk = (tid & 1) * 4;         // 0 or 4
    const float* Ag = A + (size_t)(mBase + lr)*K + lk;
    const float* Bg = Bm + (size_t)(nBase + lr)*K + lk;

    int warp = tid >> 5, lane = tid & 31;
    int wm = warp & 1, wn = warp >> 1;        // 2 x 4 warp grid
    int tm = lane & 7, tn = lane >> 3;        // 8 x 4 thread grid
    int aoff = wm*64 + tm*4;
    int boff = wn*32 + tn*4;

    float acc[8][8];
    #pragma unroll
    for (int i = 0; i < 8; i++)
        #pragma unroll
        for (int j = 0; j < 8; j++) acc[i][j] = 0.f;

    float4 pa = *(const float4*)Ag;
    float4 pb = *(const float4*)Bg;
    As[0][lk+0][lr] = pa.x; As[0][lk+1][lr] = pa.y;
    As[0][lk+2][lr] = pa.z; As[0][lk+3][lr] = pa.w;
    Bs[0][lk+0][lr] = pb.x; Bs[0][lk+1][lr] = pb.y;
    Bs[0][lk+2][lr] = pb.z; Bs[0][lk+3][lr] = pb.w;
    __syncthreads();

    int buf = 0;
    for (int kb = 8; kb <= K; kb += 8) {
        if (kb < K) {
            pa = *(const float4*)(Ag + kb);
            pb = *(const float4*)(Bg + kb);
        }
        #pragma unroll
        for (int k = 0; k < 8; k++) {
            float a[8], b[8];
            *(float4*)(a)   = *(const float4*)&As[buf][k][aoff];
            *(float4*)(a+4) = *(const float4*)&As[buf][k][aoff+32];
            *(float4*)(b)   = *(const float4*)&Bs[buf][k][boff];
            *(float4*)(b+4) = *(const float4*)&Bs[buf][k][boff+16];
            #pragma unroll
            for (int i = 0; i < 8; i++)
                #pragma unroll
                for (int j = 0; j < 8; j++) acc[i][j] += a[i]*b[j];
        }
        if (kb < K) {
            buf ^= 1;
            As[buf][lk+0][lr] = pa.x; As[buf][lk+1][lr] = pa.y;
            As[buf][lk+2][lr] = pa.z; As[buf][lk+3][lr] = pa.w;
            Bs[buf][lk+0][lr] = pb.x; Bs[buf][lk+1][lr] = pb.y;
            Bs[buf][lk+2][lr] = pb.z; Bs[buf][lk+3][lr] = pb.w;
            __syncthreads();
        }
    }

    #pragma unroll
    for (int i = 0; i < 8; i++) {
        int mloc = wm*64 + ((i < 4) ? (tm*4 + i) : (32 + tm*4 + i - 4));
        float* Cp = C + (size_t)(mBase + mloc)*N + nBase;
        if (EPI == 0) {
            *(float4*)(Cp + boff)      = make_float4(acc[i][0],acc[i][1],acc[i][2],acc[i][3]);
            *(float4*)(Cp + boff + 16) = make_float4(acc[i][4],acc[i][5],acc[i][6],acc[i][7]);
        } else {
            float4 c0 = *(const float4*)(Cp + boff);
            float4 c1 = *(const float4*)(Cp + boff + 16);
            c0.x += acc[i][0]; c0.y += acc[i][1]; c0.z += acc[i][2]; c0.w += acc[i][3];
            c1.x += acc[i][4]; c1.y += acc[i][5]; c1.z += acc[i][6]; c1.w += acc[i][7];
            *(float4*)(Cp + boff)      = c0;
            *(float4*)(Cp + boff + 16) = c1;
        }
    }
}

// ---------------- kernel 4: conv(4)+bias+silu on x-half, silu on z-half ----------
__global__ __launch_bounds__(256) void k_conv(
    const float* __restrict__ cw, const float* __restrict__ cb)
{
    int idx = blockIdx.x * blockDim.x + threadIdx.x;   // BT*DI/4
    int d = idx & (DI-1);
    int rq = idx >> 9;
    int tq = rq & (TT/4 - 1);
    size_t row0 = (size_t)rq * 4;
    const float* w = cw + d*4;
    float w0 = w[0], w1 = w[1], w2 = w[2], w3 = w[3];
    float bias = cb[d];

    float xm3 = 0.f, xm2 = 0.f, xm1 = 0.f;
    if (tq > 0) {
        xm3 = g_xz[(row0-3)*1024 + d];
        xm2 = g_xz[(row0-2)*1024 + d];
        xm1 = g_xz[(row0-1)*1024 + d];
    }
    float x0 = g_xz[(row0+0)*1024 + d];
    float x1 = g_xz[(row0+1)*1024 + d];
    float x2 = g_xz[(row0+2)*1024 + d];
    float x3 = g_xz[(row0+3)*1024 + d];

    g_xc[(row0+0)*512 + d] = siluf(bias + w0*xm3 + w1*xm2 + w2*xm1 + w3*x0);
    g_xc[(row0+1)*512 + d] = siluf(bias + w0*xm2 + w1*xm1 + w2*x0  + w3*x1);
    g_xc[(row0+2)*512 + d] = siluf(bias + w0*xm1 + w1*x0  + w2*x1  + w3*x2);
    g_xc[(row0+3)*512 + d] = siluf(bias + w0*x0  + w1*x1  + w2*x2  + w3*x3);

    #pragma unroll
    for (int i = 0; i < 4; i++) {
        float z = g_xz[(row0+i)*1024 + 512 + d];
        g_zs[(row0+i)*512 + d] = siluf(z);
    }
}

// ---------------- kernel 5: x_proj + dt_proj + softplus (fused) ------------------
__global__ __launch_bounds__(256) void k_dbc_delta(
    const float* __restrict__ xpw, const float* __restrict__ dtw,
    const float* __restrict__ dtb)
{
    __shared__ float xs[8][512];
    __shared__ float dbc_s[8][48];
    int r0 = blockIdx.x * 8;
    int tid = threadIdx.x;

    const float4* src = (const float4*)(g_xc + (size_t)r0*512);
    float4* dst = (float4*)&xs[0][0];
    #pragma unroll
    for (int i = 0; i < 4; i++) dst[tid + 256*i] = src[tid + 256*i];
    __syncthreads();

    int w = tid >> 5, lane = tid & 31;
    const float4* xr = (const float4*)xs[w];
    const float4* wp = (const float4*)xpw;
    for (int e = 0; e < 48; e++) {
        float s = 0.f;
        #pragma unroll
        for (int i = 0; i < 4; i++) {
            float4 xv = xr[lane + 32*i];
            float4 wv = __ldg(&wp[e*128 + lane + 32*i]);
            s += xv.x*wv.x + xv.y*wv.y + xv.z*wv.z + xv.w*wv.w;
        }
        #pragma unroll
        for (int o = 16; o; o >>= 1) s += __shfl_xor_sync(0xffffffffu, s, o);
        if (lane == 0) {
            dbc_s[w][e] = s;
            g_dbc[(size_t)(r0 + w)*48 + e] = s;
        }
    }
    __syncthreads();

    #pragma unroll
    for (int i = 0; i < 16; i++) {
        int idx = i*256 + tid;
        int r = idx >> 9;
        int d = idx & (DI-1);
        const float4* wr = (const float4*)(dtw + d*16);
        const float4* dr = (const float4*)dbc_s[r];
        float acc = dtb[d];
        #pragma unroll
        for (int c = 0; c < 4; c++) {
            float4 dv = dr[c];
            float4 wv = __ldg(&wr[c]);
            acc += dv.x*wv.x + dv.y*wv.y + dv.z*wv.z + dv.w*wv.w;
        }
        g_delta[(size_t)(r0 + r)*512 + d] = (acc > 20.f) ? acc : log1pf(__expf(acc));
    }
}

// ---------------- kernel 6: selective scan + D skip + gate ----------------
// one warp handles TWO channels: lanes 0..15 -> d0, lanes 16..31 -> d1.
__global__ __launch_bounds__(256) void k_scan(
    const float* __restrict__ A_log, const float* __restrict__ Dp)
{
    int gw = (blockIdx.x * blockDim.x + threadIdx.x) >> 5;   // 0..2047
    int lane = threadIdx.x & 31;
    int half = lane >> 4;
    int n = lane & 15;
    int b = gw >> 8;                 // 256 warps per batch
    int dp = gw & 255;
    int d = dp*2 + half;
    float na = -__expf(A_log[d*16 + n]);
    float Dv = Dp[d];
    float h = 0.f;
    size_t base = (size_t)b * TT;
    #pragma unroll 4
    for (int t = 0; t < TT; t++) {
        size_t row = base + t;
        float dl = __ldg(&g_delta[row*512 + d]);
        float xi = __ldg(&g_xc[row*512 + d]);
        float Bv = __ldg(&g_dbc[row*48 + 16 + n]);
        float Cv = __ldg(&g_dbc[row*48 + 32 + n]);
        float da = __expf(dl * na);
        h = da*h + (dl*xi)*Bv;
        float v = h * Cv;
        #pragma unroll
        for (int o = 8; o; o >>= 1) v += __shfl_xor_sync(0xffffffffu, v, o);
        if (n == 0) {
            float y = v + Dv*xi;
            g_y[row*512 + d] = y * __ldg(&g_zs[row*512 + d]);
        }
    }
}

// ---------------- kernel 7: final rmsnorm + head + output ----------------
__global__ __launch_bounds__(256) void k_final(
    const float* __restrict__ fw, const float* __restrict__ hw,
    const float* __restrict__ hb, float* __restrict__ out)
{
    __shared__ float red[8];
    int row = blockIdx.x;
    int m = threadIdx.x;
    float v = g_h[row*DM + m];
    float ms = blockReduceSum256(v*v, red) * (1.f/256.f);
    float hn = v * rsqrtf(ms + EPS) * fw[m];
    float dot = blockReduceSum256(hn * hw[m], red);
    if (m == 0) {
        float dlt = dot + hb[0];
        out[row] = g_past[row] + dlt;      // y
        out[BT + row] = dlt;               // delta
    }
}

// ---------------- host launcher ----------------
extern "C" void kernel_launch(void* const* d_in, const int* in_sizes, int n_in,
                              void* d_out, int out_size)
{
    const float* x    = (const float*)d_in[0];
    const float* ipw  = (const float*)d_in[1];
    const float* ipb  = (const float*)d_in[2];
    const float* lng  = (const float*)d_in[3];
    const float* lnb  = (const float*)d_in[4];
    const float* inpw = (const float*)d_in[5];   // (2,1024,256)
    const float* cw   = (const float*)d_in[6];   // (2,512,1,4)
    const float* cb   = (const float*)d_in[7];   // (2,512)
    const float* xpw  = (const float*)d_in[8];   // (2,48,512)
    const float* dtw  = (const float*)d_in[9];   // (2,512,16)
    const float* dtb  = (const float*)d_in[10];  // (2,512)
    const float* alog = (const float*)d_in[11];  // (2,512,16)
    const float* dpar = (const float*)d_in[12];  // (2,512)
    const float* opw  = (const float*)d_in[13];  // (2,256,512)
    const float* rmsw = (const float*)d_in[14];  // (2,256)
    const float* frw  = (const float*)d_in[15];  // (256)
    const float* hw   = (const float*)d_in[16];  // (1,256)
    const float* hb   = (const float*)d_in[17];  // (1)
    float* out = (float*)d_out;

    float *pu, *pxz, *py, *ph;
    cudaGetSymbolAddress((void**)&pu,  g_u);
    cudaGetSymbolAddress((void**)&pxz, g_xz);
    cudaGetSymbolAddress((void**)&py,  g_y);
    cudaGetSymbolAddress((void**)&ph,  g_h);

    k_warm<<<1, 32>>>();                        // slot filler: puts sgemm at captured position
    k_embed<<<BT, 256>>>(x, ipw, ipb, lng, lnb);

    for (int l = 0; l < 2; l++) {
        k_rms<<<BT, 256>>>(rmsw + l*DM);
        k_sgemm_nt<0><<<dim3(1024/128, BT/128), 256>>>(pu, inpw + (size_t)l*1024*256, pxz, BT, 1024, 256);
        k_conv<<<BT*DI/4/256, 256>>>(cw + l*DI*4, cb + l*DI);
        k_dbc_delta<<<BT/8, 256>>>(xpw + l*48*512, dtw + l*DI*16, dtb + l*DI);
        k_scan<<<256, 256>>>(alog + l*DI*16, dpar + l*DI);
        k_sgemm_nt<1><<<dim3(256/128, BT/128), 256>>>(py, opw + (size_t)l*256*512, ph, BT, 256, 512);
    }

    k_final<<<BT, 256>>>(frw, hw, hb, out);
}

// round 6
// speedup vs baseline: 3.1388x; 1.4454x over previous
#include <cuda_runtime.h>
#include <math.h>

#define NB    8
#define TT    2048
#define BT    (NB*TT)      // 16384 rows
#define DM    256
#define DI    512
#define EPS   1e-5f
#define CHK   32           // chunks per sequence
#define CLEN  64           // steps per chunk (CHK*CLEN = TT)
#define NWRP  (NB*(DI/2)*CHK)   // 65536 scan warps

// ---------------- scratch (device globals: no allocation allowed) ----------------
__device__ float g_h[BT*DM];        // residual stream
__device__ float g_u[BT*DM];        // rmsnorm output
__device__ float g_xz[BT*2*DI];     // in_proj output (xi | z)
__device__ float g_xc[BT*DI];       // conv+silu output
__device__ float g_zs[BT*DI];       // silu(z)
__device__ float g_dbc[BT*48];      // x_proj output (dt_in | B | C)
__device__ float g_delta[BT*DI];    // softplus(dt)
__device__ float g_y[BT*DI];        // scan output (post gate)
__device__ float g_past[BT];        // past_soc
__device__ float g_P[NWRP*32];      // chunk decay products
__device__ float g_S[NWRP*32];      // chunk local sums
__device__ float g_Hi[NWRP*32];     // chunk initial states

// ---------------- helpers ----------------
__device__ __forceinline__ float blockReduceSum256(float v, float* sh) {
    int lane = threadIdx.x & 31, wid = threadIdx.x >> 5;
    #pragma unroll
    for (int o = 16; o; o >>= 1) v += __shfl_xor_sync(0xffffffffu, v, o);
    __syncthreads();
    if (lane == 0) sh[wid] = v;
    __syncthreads();
    float s = 0.f;
    #pragma unroll
    for (int i = 0; i < 8; i++) s += sh[i];
    return s;
}

__device__ __forceinline__ float siluf(float x) {
    return x / (1.f + __expf(-x));
}

// ------- kernel 1: input proj + layernorm + past_soc + rmsnorm (layer 0) --------
__global__ __launch_bounds__(256) void k_embed(
    const float* __restrict__ x, const float* __restrict__ ipw,
    const float* __restrict__ ipb, const float* __restrict__ lng,
    const float* __restrict__ lnb, const float* __restrict__ rw)
{
    __shared__ float xs[10];
    __shared__ float red[8];
    int row = blockIdx.x;
    int m = threadIdx.x;
    if (m < 10) xs[m] = x[row*10 + m];
    __syncthreads();
    float s = ipb[m];
    #pragma unroll
    for (int i = 0; i < 10; i++) s += xs[i] * ipw[m*10 + i];
    float mean = blockReduceSum256(s, red) * (1.f/256.f);
    float d = s - mean;
    float var = blockReduceSum256(d*d, red) * (1.f/256.f);
    float hv = d * rsqrtf(var + EPS) * lng[m] + lnb[m];
    g_h[row*DM + m] = hv;
    if (m == 0) g_past[row] = xs[9];
    // fused rmsnorm for layer 0
    float ms = blockReduceSum256(hv*hv, red) * (1.f/256.f);
    g_u[row*DM + m] = hv * rsqrtf(ms + EPS) * rw[m];
}

// ---------------- kernel 2: rmsnorm of residual stream -> g_u ----------------
__global__ __launch_bounds__(256) void k_rms(const float* __restrict__ w) {
    __shared__ float red[8];
    int row = blockIdx.x;
    int m = threadIdx.x;
    float v = g_h[row*DM + m];
    float ms = blockReduceSum256(v*v, red) * (1.f/256.f);
    g_u[row*DM + m] = v * rsqrtf(ms + EPS) * w[m];
}

// ---------------- kernel 3: NT SGEMM, 128x128x8, double-buffered -----------------
template<int EPI>
__global__ __launch_bounds__(256) void k_sgemm_nt(
    const float* __restrict__ A, const float* __restrict__ Bm,
    float* __restrict__ C, int M, int N, int K)
{
    __shared__ float As[2][8][128];
    __shared__ float Bs[2][8][128];
    int tid = threadIdx.x;
    int mBase = blockIdx.y * 128, nBase = blockIdx.x * 128;

    int lr = tid >> 1;
    int lk = (tid & 1) * 4;
    const float* Ag = A + (size_t)(mBase + lr)*K + lk;
    const float* Bg = Bm + (size_t)(nBase + lr)*K + lk;

    int warp = tid >> 5, lane = tid & 31;
    int wm = warp & 1, wn = warp >> 1;
    int tm = lane & 7, tn = lane >> 3;
    int aoff = wm*64 + tm*4;
    int boff = wn*32 + tn*4;

    float acc[8][8];
    #pragma unroll
    for (int i = 0; i < 8; i++)
        #pragma unroll
        for (int j = 0; j < 8; j++) acc[i][j] = 0.f;

    float4 pa = *(const float4*)Ag;
    float4 pb = *(const float4*)Bg;
    As[0][lk+0][lr] = pa.x; As[0][lk+1][lr] = pa.y;
    As[0][lk+2][lr] = pa.z; As[0][lk+3][lr] = pa.w;
    Bs[0][lk+0][lr] = pb.x; Bs[0][lk+1][lr] = pb.y;
    Bs[0][lk+2][lr] = pb.z; Bs[0][lk+3][lr] = pb.w;
    __syncthreads();

    int buf = 0;
    for (int kb = 8; kb <= K; kb += 8) {
        if (kb < K) {
            pa = *(const float4*)(Ag + kb);
            pb = *(const float4*)(Bg + kb);
        }
        #pragma unroll
        for (int k = 0; k < 8; k++) {
            float a[8], b[8];
            *(float4*)(a)   = *(const float4*)&As[buf][k][aoff];
            *(float4*)(a+4) = *(const float4*)&As[buf][k][aoff+32];
            *(float4*)(b)   = *(const float4*)&Bs[buf][k][boff];
            *(float4*)(b+4) = *(const float4*)&Bs[buf][k][boff+16];
            #pragma unroll
            for (int i = 0; i < 8; i++)
                #pragma unroll
                for (int j = 0; j < 8; j++) acc[i][j] += a[i]*b[j];
        }
        if (kb < K) {
            buf ^= 1;
            As[buf][lk+0][lr] = pa.x; As[buf][lk+1][lr] = pa.y;
            As[buf][lk+2][lr] = pa.z; As[buf][lk+3][lr] = pa.w;
            Bs[buf][lk+0][lr] = pb.x; Bs[buf][lk+1][lr] = pb.y;
            Bs[buf][lk+2][lr] = pb.z; Bs[buf][lk+3][lr] = pb.w;
            __syncthreads();
        }
    }

    #pragma unroll
    for (int i = 0; i < 8; i++) {
        int mloc = wm*64 + ((i < 4) ? (tm*4 + i) : (32 + tm*4 + i - 4));
        float* Cp = C + (size_t)(mBase + mloc)*N + nBase;
        if (EPI == 0) {
            *(float4*)(Cp + boff)      = make_float4(acc[i][0],acc[i][1],acc[i][2],acc[i][3]);
            *(float4*)(Cp + boff + 16) = make_float4(acc[i][4],acc[i][5],acc[i][6],acc[i][7]);
        } else {
            float4 c0 = *(const float4*)(Cp + boff);
            float4 c1 = *(const float4*)(Cp + boff + 16);
            c0.x += acc[i][0]; c0.y += acc[i][1]; c0.z += acc[i][2]; c0.w += acc[i][3];
            c1.x += acc[i][4]; c1.y += acc[i][5]; c1.z += acc[i][6]; c1.w += acc[i][7];
            *(float4*)(Cp + boff)      = c0;
            *(float4*)(Cp + boff + 16) = c1;
        }
    }
}

// ------ kernel 4: FUSED conv+silu (+z-silu) + x_proj + dt_proj + softplus --------
// 8 rows per block.
__global__ __launch_bounds__(256) void k_convdbc(
    const float* __restrict__ cw, const float* __restrict__ cb,
    const float* __restrict__ xpw, const float* __restrict__ dtw,
    const float* __restrict__ dtb)
{
    __shared__ float xs[8][512];
    __shared__ float dbc_s[8][48];
    int r0 = blockIdx.x * 8;          // 8-row aligned -> t0 is 0 or >=8
    int tid = threadIdx.x;

    // conv phase: 1024 items = (rg in 0..1) x (d in 0..511), 4 rows per item
    #pragma unroll
    for (int i = 0; i < 4; i++) {
        int item = i*256 + tid;
        int rg = item >> 9;
        int d = item & (DI-1);
        size_t row0 = (size_t)r0 + rg*4;
        int t0 = (int)(row0 & (TT-1));
        const float* w = cw + d*4;
        float w0 = w[0], w1 = w[1], w2 = w[2], w3 = w[3];
        float bias = cb[d];

        float xm3 = 0.f, xm2 = 0.f, xm1 = 0.f;
        if (t0 > 0) {
            xm3 = g_xz[(row0-3)*1024 + d];
            xm2 = g_xz[(row0-2)*1024 + d];
            xm1 = g_xz[(row0-1)*1024 + d];
        }
        float x0 = g_xz[(row0+0)*1024 + d];
        float x1 = g_xz[(row0+1)*1024 + d];
        float x2 = g_xz[(row0+2)*1024 + d];
        float x3 = g_xz[(row0+3)*1024 + d];

        float c0 = siluf(bias + w0*xm3 + w1*xm2 + w2*xm1 + w3*x0);
        float c1 = siluf(bias + w0*xm2 + w1*xm1 + w2*x0  + w3*x1);
        float c2 = siluf(bias + w0*xm1 + w1*x0  + w2*x1  + w3*x2);
        float c3 = siluf(bias + w0*x0  + w1*x1  + w2*x2  + w3*x3);
        int lr = rg*4;
        xs[lr+0][d] = c0; xs[lr+1][d] = c1; xs[lr+2][d] = c2; xs[lr+3][d] = c3;
        g_xc[(row0+0)*512 + d] = c0;
        g_xc[(row0+1)*512 + d] = c1;
        g_xc[(row0+2)*512 + d] = c2;
        g_xc[(row0+3)*512 + d] = c3;
        #pragma unroll
        for (int j = 0; j < 4; j++) {
            float z = g_xz[(row0+j)*1024 + 512 + d];
            g_zs[(row0+j)*512 + d] = siluf(z);
        }
    }
    __syncthreads();

    // x_proj phase: warp per row, 48 dots of 512
    int w = tid >> 5, lane = tid & 31;
    const float4* xr = (const float4*)xs[w];
    const float4* wp = (const float4*)xpw;
    for (int e = 0; e < 48; e++) {
        float s = 0.f;
        #pragma unroll
        for (int i = 0; i < 4; i++) {
            float4 xv = xr[lane + 32*i];
            float4 wv = __ldg(&wp[e*128 + lane + 32*i]);
            s += xv.x*wv.x + xv.y*wv.y + xv.z*wv.z + xv.w*wv.w;
        }
        #pragma unroll
        for (int o = 16; o; o >>= 1) s += __shfl_xor_sync(0xffffffffu, s, o);
        if (lane == 0) {
            dbc_s[w][e] = s;
            g_dbc[(size_t)(r0 + w)*48 + e] = s;
        }
    }
    __syncthreads();

    // dt_proj + softplus phase
    #pragma unroll
    for (int i = 0; i < 16; i++) {
        int idx = i*256 + tid;
        int r = idx >> 9;
        int d = idx & (DI-1);
        const float4* wr = (const float4*)(dtw + d*16);
        const float4* dr = (const float4*)dbc_s[r];
        float acc = dtb[d];
        #pragma unroll
        for (int c = 0; c < 4; c++) {
            float4 dv = dr[c];
            float4 wv = __ldg(&wr[c]);
            acc += dv.x*wv.x + dv.y*wv.y + dv.z*wv.z + dv.w*wv.w;
        }
        g_delta[(size_t)(r0 + r)*512 + d] = (acc > 20.f) ? acc : log1pf(__expf(acc));
    }
}

// -------- kernel 5a: scan pass A — per-chunk (P = prod dA, S = local h) ----------
// warp = (b, d-pair, chunk); lanes 0..15 -> d0, 16..31 -> d1.
__global__ __launch_bounds__(256) void k_scanA(const float* __restrict__ A_log) {
    int gw = blockIdx.x*8 + (threadIdx.x >> 5);    // 0..NWRP-1
    int lane = threadIdx.x & 31;
    int c = gw & (CHK-1);
    int dp = (gw >> 5) & 255;
    int b = gw >> 13;
    int half = lane >> 4, n = lane & 15;
    int d = dp*2 + half;
    float na = -__expf(A_log[d*16 + n]);
    float P = 1.f, S = 0.f;
    size_t row = (size_t)b*TT + c*CLEN;
    #pragma unroll 4
    for (int t = 0; t < CLEN; t++, row++) {
        float dl = __ldg(&g_delta[row*512 + d]);
        float xi = __ldg(&g_xc[row*512 + d]);
        float Bv = __ldg(&g_dbc[row*48 + 16 + n]);
        float da = __expf(dl * na);
        P *= da;
        S = da*S + (dl*xi)*Bv;
    }
    size_t o = (size_t)gw*32 + lane;
    g_P[o] = P;
    g_S[o] = S;
}

// -------- kernel 5b: scan pass B — serial prefix over the 32 chunks --------------
__global__ __launch_bounds__(256) void k_scanB() {
    int t = blockIdx.x*256 + threadIdx.x;    // 0..65535
    int lane = t & 31;
    int wdp = t >> 5;                        // (b*256 + dp)
    float h = 0.f;
    #pragma unroll
    for (int c = 0; c < CHK; c++) {
        size_t o = ((size_t)wdp*CHK + c)*32 + lane;
        g_Hi[o] = h;
        h = g_P[o]*h + g_S[o];
    }
}

// -------- kernel 5c: scan pass C — re-run chunk from Hinit, emit outputs ---------
__global__ __launch_bounds__(256) void k_scanC(
    const float* __restrict__ A_log, const float* __restrict__ Dp)
{
    int gw = blockIdx.x*8 + (threadIdx.x >> 5);
    int lane = threadIdx.x & 31;
    int c = gw & (CHK-1);
    int dp = (gw >> 5) & 255;
    int b = gw >> 13;
    int half = lane >> 4, n = lane & 15;
    int d = dp*2 + half;
    float na = -__expf(A_log[d*16 + n]);
    float Dv = Dp[d];
    float h = g_Hi[(size_t)gw*32 + lane];
    size_t row = (size_t)b*TT + c*CLEN;
    #pragma unroll 4
    for (int t = 0; t < CLEN; t++, row++) {
        float dl = __ldg(&g_delta[row*512 + d]);
        float xi = __ldg(&g_xc[row*512 + d]);
        float Bv = __ldg(&g_dbc[row*48 + 16 + n]);
        float Cv = __ldg(&g_dbc[row*48 + 32 + n]);
        float da = __expf(dl * na);
        h = da*h + (dl*xi)*Bv;
        float v = h * Cv;
        #pragma unroll
        for (int o = 8; o; o >>= 1) v += __shfl_xor_sync(0xffffffffu, v, o);
        if (n == 0) {
            float y = v + Dv*xi;
            g_y[row*512 + d] = y * __ldg(&g_zs[row*512 + d]);
        }
    }
}

// ---------------- kernel 6: final rmsnorm + head + output ----------------
__global__ __launch_bounds__(256) void k_final(
    const float* __restrict__ fw, const float* __restrict__ hw,
    const float* __restrict__ hb, float* __restrict__ out)
{
    __shared__ float red[8];
    int row = blockIdx.x;
    int m = threadIdx.x;
    float v = g_h[row*DM + m];
    float ms = blockReduceSum256(v*v, red) * (1.f/256.f);
    float hn = v * rsqrtf(ms + EPS) * fw[m];
    float dot = blockReduceSum256(hn * hw[m], red);
    if (m == 0) {
        float dlt = dot + hb[0];
        out[row] = g_past[row] + dlt;      // y
        out[BT + row] = dlt;               // delta
    }
}

// ---------------- host launcher ----------------
extern "C" void kernel_launch(void* const* d_in, const int* in_sizes, int n_in,
                              void* d_out, int out_size)
{
    const float* x    = (const float*)d_in[0];
    const float* ipw  = (const float*)d_in[1];
    const float* ipb  = (const float*)d_in[2];
    const float* lng  = (const float*)d_in[3];
    const float* lnb  = (const float*)d_in[4];
    const float* inpw = (const float*)d_in[5];   // (2,1024,256)
    const float* cw   = (const float*)d_in[6];   // (2,512,1,4)
    const float* cb   = (const float*)d_in[7];   // (2,512)
    const float* xpw  = (const float*)d_in[8];   // (2,48,512)
    const float* dtw  = (const float*)d_in[9];   // (2,512,16)
    const float* dtb  = (const float*)d_in[10];  // (2,512)
    const float* alog = (const float*)d_in[11];  // (2,512,16)
    const float* dpar = (const float*)d_in[12];  // (2,512)
    const float* opw  = (const float*)d_in[13];  // (2,256,512)
    const float* rmsw = (const float*)d_in[14];  // (2,256)
    const float* frw  = (const float*)d_in[15];  // (256)
    const float* hw   = (const float*)d_in[16];  // (1,256)
    const float* hb   = (const float*)d_in[17];  // (1)
    float* out = (float*)d_out;

    float *pu, *pxz, *py, *ph;
    cudaGetSymbolAddress((void**)&pu,  g_u);
    cudaGetSymbolAddress((void**)&pxz, g_xz);
    cudaGetSymbolAddress((void**)&py,  g_y);
    cudaGetSymbolAddress((void**)&ph,  g_h);

    // launch order puts k_scanA at captured slot #4
    k_embed<<<BT, 256>>>(x, ipw, ipb, lng, lnb, rmsw);   // includes layer-0 rmsnorm

    for (int l = 0; l < 2; l++) {
        if (l > 0) k_rms<<<BT, 256>>>(rmsw + l*DM);
        k_sgemm_nt<0><<<dim3(1024/128, BT/128), 256>>>(pu, inpw + (size_t)l*1024*256, pxz, BT, 1024, 256);
        k_convdbc<<<BT/8, 256>>>(cw + l*DI*4, cb + l*DI, xpw + l*48*512, dtw + l*DI*16, dtb + l*DI);
        k_scanA<<<NWRP/8, 256>>>(alog + l*DI*16);
        k_scanB<<<256, 256>>>();
        k_scanC<<<NWRP/8, 256>>>(alog + l*DI*16, dpar + l*DI);
        k_sgemm_nt<1><<<dim3(256/128, BT/128), 256>>>(py, opw + (size_t)l*256*512, ph, BT, 256, 512);
    }

    k_final<<<BT, 256>>>(frw, hw, hb, out);
}